// round 10
// baseline (speedup 1.0000x reference)
#include <cuda_runtime.h>
#include <stdint.h>

// Sort_Latent_Layer: z (B, 1, 8192) fp32. Per row: 512 packets x 16 floats,
// stable-sort packets by packet[0] ascending, gather, write back.
//
// R9: two passes, each shape-optimal.
//   Pass 1: warp-per-row register/shfl bitonic sort -> u16 permutation
//           (reads 16KB key sectors/row, writes 1KB perm/row, coalesced).
//   Pass 2: streaming permuted copy, CTA-per-row, 256 thr x 8 float4:
//           coalesced writes, 64B-contiguous random packet reads, __ldcs/__stcs.
// Traffic: 64 + 4 + 4 + 128 + 128 = 328 MB, all at streaming-friendly shapes.

#define NPK 512
#define V   16
#define WARPS_PER_CTA 4
#define P1_THREADS (32 * WARPS_PER_CTA)
#define MAX_B 4096

__device__ uint16_t g_perm[MAX_B * NPK];   // 4 MB scratch (allowed: device global)

__device__ __forceinline__ void ce(unsigned long long &x, unsigned long long &y, bool up)
{
    bool sw = (x > y) == up;          // items are distinct (idx in low bits)
    unsigned long long a = sw ? y : x;
    unsigned long long b = sw ? x : y;
    x = a; y = b;
}

// ---------------- Pass 1: permutation ----------------
__global__ void __launch_bounds__(P1_THREADS)
perm_kernel(const float* __restrict__ z, int B)
{
    __shared__ uint32_t sperm[WARPS_PER_CTA][NPK / 2];

    const int lane = threadIdx.x & 31;
    const int w    = threadIdx.x >> 5;
    const int row  = blockIdx.x * WARPS_PER_CTA + w;
    if (row >= B) return;

    const float* __restrict__ zr = z + (long long)row * 8192;

    // keys: strided 64B -> 32B sectors, streaming (no reuse intended)
    unsigned long long it[V];
    #pragma unroll
    for (int v = 0; v < V; ++v) {
        int i = lane * V + v;                   // blocked item assignment
        uint32_t kb = __float_as_uint(__ldcs(zr + i * 16));
        kb = (kb & 0x80000000u) ? ~kb : (kb | 0x80000000u);   // monotone
        it[v] = ((unsigned long long)kb << 32) | (unsigned)i;
    }

    // bitonic sort, 512 items: register-local (j<16) + shfl (j>=16)
    #pragma unroll
    for (int k = 2; k <= V; k <<= 1) {
        #pragma unroll
        for (int j = k >> 1; j >= 1; j >>= 1) {
            #pragma unroll
            for (int v = 0; v < V; ++v) {
                if ((v & j) == 0) {
                    int i = lane * V + v;
                    bool up = ((i & k) == 0);
                    ce(it[v], it[v | j], up);
                }
            }
        }
    }
    #pragma unroll
    for (int k = 32; k <= 512; k <<= 1) {
        const bool up = ((lane & (k >> 4)) == 0);
        #pragma unroll
        for (int j = k >> 1; j >= V; j >>= 1) {
            const int  dl      = j >> 4;
            const bool keepmin = (((lane & dl) == 0) == up);
            #pragma unroll
            for (int v = 0; v < V; ++v) {
                unsigned long long other = __shfl_xor_sync(0xFFFFFFFFu, it[v], dl);
                if ((other < it[v]) == keepmin) it[v] = other;
            }
        }
        #pragma unroll
        for (int j = V >> 1; j >= 1; j >>= 1) {
            #pragma unroll
            for (int v = 0; v < V; ++v)
                if ((v & j) == 0) ce(it[v], it[v | j], up);
        }
    }

    // publish packed pairs to smem, then coalesced global write
    uint32_t* sp = sperm[w];
    #pragma unroll
    for (int v = 0; v < V; v += 2) {
        uint32_t lo = (uint32_t)(it[v]     & 0x1FFu);
        uint32_t hi = (uint32_t)(it[v + 1] & 0x1FFu);
        sp[(lane * V + v) >> 1] = lo | (hi << 16);
    }
    __syncwarp();

    uint32_t* gp = (uint32_t*)(g_perm + (long long)row * NPK);
    #pragma unroll
    for (int jj = 0; jj < (NPK / 2) / 32; ++jj)
        gp[jj * 32 + lane] = sp[jj * 32 + lane];
}

// ---------------- Pass 2: streaming permuted copy ----------------
#define P2_THREADS 256
#define P2_ITERS   8        // 256 * 8 = 2048 float4 = one row

__global__ void __launch_bounds__(P2_THREADS)
gather_kernel(const float* __restrict__ z, float* __restrict__ out)
{
    const int row = blockIdx.x;
    const int tid = threadIdx.x;

    const float4* __restrict__   in4  = (const float4*)(z   + (long long)row * 8192);
    float4* __restrict__         out4 = (float4*)(out + (long long)row * 8192);
    const uint16_t* __restrict__ p    = g_perm + (long long)row * NPK;

    int   src[P2_ITERS];
    float4 v4[P2_ITERS];

    #pragma unroll
    for (int u = 0; u < P2_ITERS; ++u) {
        int f = u * P2_THREADS + tid;
        src[u] = __ldg(p + (f >> 2));
    }
    #pragma unroll
    for (int u = 0; u < P2_ITERS; ++u) {
        int f = u * P2_THREADS + tid;
        v4[u] = __ldcs(&in4[src[u] * 4 + (f & 3)]);   // streaming read, full 64B packets
    }
    #pragma unroll
    for (int u = 0; u < P2_ITERS; ++u) {
        int f = u * P2_THREADS + tid;
        __stcs(&out4[f], v4[u]);                      // coalesced streaming write
    }
}

extern "C" void kernel_launch(void* const* d_in, const int* in_sizes, int n_in,
                              void* d_out, int out_size)
{
    const float* z = (const float*)d_in[0];
    float* out     = (float*)d_out;
    const int D = 8192;                  // 512 packets * 16 floats
    int B = in_sizes[0] / D;             // 4096

    int grid1 = (B + WARPS_PER_CTA - 1) / WARPS_PER_CTA;
    perm_kernel<<<grid1, P1_THREADS>>>(z, B);
    gather_kernel<<<B, P2_THREADS>>>(z, out);
}

// round 11
// speedup vs baseline: 1.0259x; 1.0259x over previous
#include <cuda_runtime.h>
#include <stdint.h>

// Sort_Latent_Layer: z (B, 1, 8192) fp32. Per row: 512 packets x 16 floats,
// stable-sort packets by packet[0] ascending, gather, write back.
//
// R10: two passes.
//   Pass 1 (perm): warp-per-row register/shfl bitonic sort.
//     NEW: keys loaded CYCLICALLY (lane reads packets vs*32+lane -> 16 lines
//     per LDG instead of 32), then transposed cyclic->blocked through a
//     padded smem tile (conflict-free STS.32 / LDS.128).
//   Pass 2 (gather): CTA-per-row streaming permuted copy (validated 38.7us,
//     ~traffic floor): coalesced writes, 64B-contiguous random packet reads.

#define NPK 512
#define V   16
#define WARPS_PER_CTA 4
#define P1_THREADS (32 * WARPS_PER_CTA)
#define MAX_B 4096

// padded transpose tile: off(i) = (i>>5)*36 + (i&31), max 15*36+31 = 571 words
#define TPAD   36
#define TWORDS 576

__device__ uint16_t g_perm[MAX_B * NPK];   // 4 MB scratch (device global: allowed)

__device__ __forceinline__ void ce(unsigned long long &x, unsigned long long &y, bool up)
{
    bool sw = (x > y) == up;          // items are distinct (idx in low bits)
    unsigned long long a = sw ? y : x;
    unsigned long long b = sw ? x : y;
    x = a; y = b;
}

// ---------------- Pass 1: permutation ----------------
__global__ void __launch_bounds__(P1_THREADS)
perm_kernel(const float* __restrict__ z, int B)
{
    __shared__ uint32_t skey[WARPS_PER_CTA][TWORDS];     // 9.2 KB
    __shared__ uint32_t sperm[WARPS_PER_CTA][NPK / 2];   // 4 KB

    const int lane = threadIdx.x & 31;
    const int w    = threadIdx.x >> 5;
    const int row  = blockIdx.x * WARPS_PER_CTA + w;
    if (row >= B) return;

    const float* __restrict__ zr = z + (long long)row * 8192;
    uint32_t* sk = skey[w];

    // ---- coalesced cyclic key load: item i = vs*32 + lane ----
    // lane stride 64B -> 16 lines per LDG (vs blocked's 32). Monotone-map and
    // stage into padded smem at off(i) = (i>>5)*36 + (i&31)  (STS conflict-free).
    #pragma unroll
    for (int vs = 0; vs < V; ++vs) {
        uint32_t kb = __float_as_uint(__ldcs(zr + (vs * 32 + lane) * 16));
        kb = (kb & 0x80000000u) ? ~kb : (kb | 0x80000000u);
        sk[vs * TPAD + lane] = kb;
    }
    __syncwarp();

    // ---- blocked read-back: it[v] = item lane*16 + v ----
    // off = (lane>>1)*36 + (lane&1)*16 + v  -> LDS.128 x4, conflict-free phases.
    unsigned long long it[V];
    {
        const uint32_t base = (uint32_t)(lane >> 1) * TPAD + (uint32_t)(lane & 1) * 16;
        #pragma unroll
        for (int t = 0; t < V / 4; ++t) {
            uint4 kk = *reinterpret_cast<const uint4*>(sk + base + t * 4);
            int i0 = lane * V + t * 4;
            it[t * 4 + 0] = ((unsigned long long)kk.x << 32) | (unsigned)(i0 + 0);
            it[t * 4 + 1] = ((unsigned long long)kk.y << 32) | (unsigned)(i0 + 1);
            it[t * 4 + 2] = ((unsigned long long)kk.z << 32) | (unsigned)(i0 + 2);
            it[t * 4 + 3] = ((unsigned long long)kk.w << 32) | (unsigned)(i0 + 3);
        }
    }

    // ---- bitonic sort, 512 items: register-local (j<16) + shfl (j>=16) ----
    #pragma unroll
    for (int k = 2; k <= V; k <<= 1) {
        #pragma unroll
        for (int j = k >> 1; j >= 1; j >>= 1) {
            #pragma unroll
            for (int v = 0; v < V; ++v) {
                if ((v & j) == 0) {
                    int i = lane * V + v;
                    bool up = ((i & k) == 0);
                    ce(it[v], it[v | j], up);
                }
            }
        }
    }
    #pragma unroll
    for (int k = 32; k <= 512; k <<= 1) {
        const bool up = ((lane & (k >> 4)) == 0);
        #pragma unroll
        for (int j = k >> 1; j >= V; j >>= 1) {
            const int  dl      = j >> 4;
            const bool keepmin = (((lane & dl) == 0) == up);
            #pragma unroll
            for (int v = 0; v < V; ++v) {
                unsigned long long other = __shfl_xor_sync(0xFFFFFFFFu, it[v], dl);
                if ((other < it[v]) == keepmin) it[v] = other;
            }
        }
        #pragma unroll
        for (int j = V >> 1; j >= 1; j >>= 1) {
            #pragma unroll
            for (int v = 0; v < V; ++v)
                if ((v & j) == 0) ce(it[v], it[v | j], up);
        }
    }

    // ---- publish packed pairs to smem, then coalesced global write ----
    uint32_t* sp = sperm[w];
    #pragma unroll
    for (int v = 0; v < V; v += 2) {
        uint32_t lo = (uint32_t)(it[v]     & 0x1FFu);
        uint32_t hi = (uint32_t)(it[v + 1] & 0x1FFu);
        sp[(lane * V + v) >> 1] = lo | (hi << 16);
    }
    __syncwarp();

    uint32_t* gp = (uint32_t*)(g_perm + (long long)row * NPK);
    #pragma unroll
    for (int jj = 0; jj < (NPK / 2) / 32; ++jj)
        __stcs(gp + jj * 32 + lane, sp[jj * 32 + lane]);
}

// ---------------- Pass 2: streaming permuted copy ----------------
#define P2_THREADS 256
#define P2_ITERS   8        // 256 * 8 = 2048 float4 = one row

__global__ void __launch_bounds__(P2_THREADS)
gather_kernel(const float* __restrict__ z, float* __restrict__ out)
{
    const int row = blockIdx.x;
    const int tid = threadIdx.x;

    const float4* __restrict__   in4  = (const float4*)(z   + (long long)row * 8192);
    float4* __restrict__         out4 = (float4*)(out + (long long)row * 8192);
    const uint16_t* __restrict__ p    = g_perm + (long long)row * NPK;

    int    src[P2_ITERS];
    float4 v4[P2_ITERS];

    #pragma unroll
    for (int u = 0; u < P2_ITERS; ++u) {
        int f = u * P2_THREADS + tid;
        src[u] = __ldg(p + (f >> 2));
    }
    #pragma unroll
    for (int u = 0; u < P2_ITERS; ++u) {
        int f = u * P2_THREADS + tid;
        v4[u] = __ldcs(&in4[src[u] * 4 + (f & 3)]);   // streaming 64B-packet reads
    }
    #pragma unroll
    for (int u = 0; u < P2_ITERS; ++u) {
        int f = u * P2_THREADS + tid;
        __stcs(&out4[f], v4[u]);                      // coalesced streaming write
    }
}

extern "C" void kernel_launch(void* const* d_in, const int* in_sizes, int n_in,
                              void* d_out, int out_size)
{
    const float* z = (const float*)d_in[0];
    float* out     = (float*)d_out;
    const int D = 8192;                  // 512 packets * 16 floats
    int B = in_sizes[0] / D;             // 4096

    int grid1 = (B + WARPS_PER_CTA - 1) / WARPS_PER_CTA;
    perm_kernel<<<grid1, P1_THREADS>>>(z, B);
    gather_kernel<<<B, P2_THREADS>>>(z, out);
}

// round 12
// speedup vs baseline: 1.1353x; 1.1066x over previous
#include <cuda_runtime.h>
#include <stdint.h>

// Sort_Latent_Layer: z (B, 1, 8192) fp32. Per row: 512 packets x 16 floats,
// stable-sort packets by packet[0] ascending, gather, write back.
//
// R11: fused warp-per-row kernel, tuned for concurrency:
//   - 2-warp CTAs, __launch_bounds__(64,16) -> 64-reg cap -> up to 32 warps/SM
//     (R8's fused design ran only ~17 warps/SM and left DRAM at 58%).
//   - cyclic key load (16 lines/LDG) + padded smem transpose (R10, validated).
//   - register/shfl bitonic sort, 512 items (bit-exact since R4).
//   - gather global->global: __ldcs 64B-packet reads, __stcs coalesced writes,
//     batched 8x for MLP. Traffic ~324 MB total (R8-measured shape).

#define NPK 512
#define V   16
#define WARPS_PER_CTA 2
#define THREADS (32 * WARPS_PER_CTA)

// padded transpose tile: off(i) = (i>>5)*36 + (i&31)
#define TPAD   36
#define TWORDS 576

__device__ __forceinline__ void ce(unsigned long long &x, unsigned long long &y, bool up)
{
    bool sw = (x > y) == up;          // items are distinct (idx in low bits)
    unsigned long long a = sw ? y : x;
    unsigned long long b = sw ? x : y;
    x = a; y = b;
}

__global__ void __launch_bounds__(THREADS, 16)
sort_latent_kernel(const float* __restrict__ z, float* __restrict__ out, int B)
{
    __shared__ uint32_t skey [WARPS_PER_CTA][TWORDS];    // 4.6 KB
    __shared__ uint32_t sperm[WARPS_PER_CTA][NPK / 2];   // 2 KB

    const int lane = threadIdx.x & 31;
    const int w    = threadIdx.x >> 5;
    const int row  = blockIdx.x * WARPS_PER_CTA + w;
    if (row >= B) return;                         // whole-warp exit

    const float* __restrict__ zr = z + (long long)row * 8192;
    uint32_t* sk = skey[w];

    // ---- cyclic key load: item i = vs*32 + lane (16 lines/LDG) ----
    #pragma unroll
    for (int vs = 0; vs < V; ++vs) {
        uint32_t kb = __float_as_uint(__ldcs(zr + (vs * 32 + lane) * 16));
        kb = (kb & 0x80000000u) ? ~kb : (kb | 0x80000000u);   // monotone map
        sk[vs * TPAD + lane] = kb;
    }
    __syncwarp();

    // ---- blocked read-back: it[v] = item lane*16 + v (LDS.128, conflict-free) ----
    unsigned long long it[V];
    {
        const uint32_t base = (uint32_t)(lane >> 1) * TPAD + (uint32_t)(lane & 1) * 16;
        #pragma unroll
        for (int t = 0; t < V / 4; ++t) {
            uint4 kk = *reinterpret_cast<const uint4*>(sk + base + t * 4);
            int i0 = lane * V + t * 4;
            it[t * 4 + 0] = ((unsigned long long)kk.x << 32) | (unsigned)(i0 + 0);
            it[t * 4 + 1] = ((unsigned long long)kk.y << 32) | (unsigned)(i0 + 1);
            it[t * 4 + 2] = ((unsigned long long)kk.z << 32) | (unsigned)(i0 + 2);
            it[t * 4 + 3] = ((unsigned long long)kk.w << 32) | (unsigned)(i0 + 3);
        }
    }

    // ---- bitonic sort, 512 items: register-local (j<16) + shfl (j>=16) ----
    #pragma unroll
    for (int k = 2; k <= V; k <<= 1) {
        #pragma unroll
        for (int j = k >> 1; j >= 1; j >>= 1) {
            #pragma unroll
            for (int v = 0; v < V; ++v) {
                if ((v & j) == 0) {
                    int i = lane * V + v;
                    bool up = ((i & k) == 0);
                    ce(it[v], it[v | j], up);
                }
            }
        }
    }
    #pragma unroll
    for (int k = 32; k <= 512; k <<= 1) {
        const bool up = ((lane & (k >> 4)) == 0);
        #pragma unroll
        for (int j = k >> 1; j >= V; j >>= 1) {
            const int  dl      = j >> 4;
            const bool keepmin = (((lane & dl) == 0) == up);
            #pragma unroll
            for (int v = 0; v < V; ++v) {
                unsigned long long other = __shfl_xor_sync(0xFFFFFFFFu, it[v], dl);
                if ((other < it[v]) == keepmin) it[v] = other;
            }
        }
        #pragma unroll
        for (int j = V >> 1; j >= 1; j >>= 1) {
            #pragma unroll
            for (int v = 0; v < V; ++v)
                if ((v & j) == 0) ce(it[v], it[v | j], up);
        }
    }

    // ---- publish permutation (pairs packed into u32 stores) ----
    uint32_t* sp = sperm[w];
    #pragma unroll
    for (int v = 0; v < V; v += 2) {
        uint32_t lo = (uint32_t)(it[v]     & 0x1FFu);
        uint32_t hi = (uint32_t)(it[v + 1] & 0x1FFu);
        sp[(lane * V + v) >> 1] = lo | (hi << 16);
    }
    __syncwarp();

    // ---- gather global->global, batched for MLP ----
    const uint16_t* p = (const uint16_t*)sp;
    const float4* __restrict__ in4  = (const float4*)zr;
    float4* __restrict__       out4 = (float4*)(out + (long long)row * 8192);

    #pragma unroll 1
    for (int blk = 0; blk < 64; blk += 8) {
        float4 v4[8];
        #pragma unroll
        for (int u = 0; u < 8; ++u) {
            int f   = (blk + u) * 32 + lane;
            int src = p[f >> 2];
            v4[u] = __ldcs(&in4[src * 4 + (f & 3)]);   // streaming 64B-packet read
        }
        #pragma unroll
        for (int u = 0; u < 8; ++u) {
            int f = (blk + u) * 32 + lane;
            __stcs(&out4[f], v4[u]);                    // coalesced streaming write
        }
    }
}

extern "C" void kernel_launch(void* const* d_in, const int* in_sizes, int n_in,
                              void* d_out, int out_size)
{
    const float* z = (const float*)d_in[0];
    float* out     = (float*)d_out;
    const int D = 8192;                  // 512 packets * 16 floats
    int B = in_sizes[0] / D;             // 4096

    int grid = (B + WARPS_PER_CTA - 1) / WARPS_PER_CTA;   // 2048 CTAs, warp-per-row
    sort_latent_kernel<<<grid, THREADS>>>(z, out, B);
}